// round 15
// baseline (speedup 1.0000x reference)
#include <cuda_runtime.h>
#include <cmath>

#define NLEVELS 16
#define TBL 524288u          /* hashmap size, power of 2 */
#define BLOCK 256            /* threads; 128 points per block (2 threads/point) */
#define PTS   128

struct LevelParams {
    float    scale[NLEVELS];
    unsigned res[NLEVELS];
    unsigned off[NLEVELS];   /* offset into latents, in float2 entries */
    int      fhl;            /* first hash level */
};

/* 4 corner indices for this thread's y-half (ABSOLUTE, offset folded in).
   Corner slots: v[0]=(x0,z0) v[1]=(x0,z1) v[2]=(x1,z0) v[3]=(x1,z1);
   x-merge pairs are (0,2) and (1,3). */
__device__ __forceinline__ void calc_level_half(const LevelParams& lp, int l, int half,
                                                float px, float py, float pz,
                                                unsigned idx[4],
                                                float& rx, float& ry, float& rz)
{
    const float s = lp.scale[l];
    /* match reference: separate mul then add (no fma contraction) */
    const float sx = __fadd_rn(__fmul_rn(px, s), 0.5f);
    const float sy = __fadd_rn(__fmul_rn(py, s), 0.5f);
    const float sz = __fadd_rn(__fmul_rn(pz, s), 0.5f);
    const float fx = floorf(sx), fy = floorf(sy), fz = floorf(sz);
    rx = sx - fx; ry = sy - fy; rz = sz - fz;
    const unsigned x0 = (unsigned)fx;
    const unsigned yh = (unsigned)fy + (unsigned)half;
    const unsigned z0 = (unsigned)fz;
    const unsigned off = lp.off[l];

    if (l < lp.fhl) {
        const unsigned r  = lp.res[l];
        const unsigned r2 = r * r;
        const unsigned base = off + x0 + yh * r + z0 * r2;  /* strides [1, r, r^2] */
        idx[0] = base;
        idx[1] = base + r2;
        idx[2] = base + 1u;
        idx[3] = base + 1u + r2;
    } else {
        const unsigned hy  = yh * 2654435761u;
        const unsigned hz0 = z0 * 805459861u;
        const unsigned hz1 = hz0 + 805459861u;
        const unsigned m = TBL - 1u;
        const unsigned x1 = x0 + 1u;
        idx[0] = off + ((x0 ^ hy ^ hz0) & m);
        idx[1] = off + ((x0 ^ hy ^ hz1) & m);
        idx[2] = off + ((x1 ^ hy ^ hz0) & m);
        idx[3] = off + ((x1 ^ hy ^ hz1) & m);
    }
}

/* 4 gathers (2 x-pairs); merge a pair into one aligned float4 when the absolute
   indices are {2k, 2k+1} (guarantees 16B alignment; latents base >=256B aligned). */
__device__ __forceinline__ void load_level_half(const float2* __restrict__ lat,
                                                const unsigned idx[4], float2 v[4])
{
#pragma unroll
    for (int k = 0; k < 2; ++k) {
        const unsigned a = idx[k];
        const unsigned b = idx[k + 2];
        if ((a ^ b) == 1u) {
            const float4 q = __ldg(reinterpret_cast<const float4*>(lat) + (a >> 1));
            const float2 lo = make_float2(q.x, q.y);
            const float2 hi = make_float2(q.z, q.w);
            if (a & 1u) { v[k] = hi; v[k + 2] = lo; }
            else        { v[k] = lo; v[k + 2] = hi; }
        } else {
            v[k]     = __ldg(lat + a);
            v[k + 2] = __ldg(lat + b);
        }
    }
}

__global__ __launch_bounds__(BLOCK, 4)
void hashgrid_enc_kernel(const float* __restrict__ pos,
                         const float* __restrict__ latents,
                         float* __restrict__ out,
                         int n_points, LevelParams lp)
{
    /* 32 feature rows x 128 points, pad 129 for conflict-free transpose */
    __shared__ float s_out[32 * 129];

    const int tid  = threadIdx.x;
    const int half = tid & 1;            /* y-corner half this thread owns */
    const int pl   = tid >> 1;           /* point-in-block 0..127 */
    const int p    = blockIdx.x * PTS + pl;
    const int pc   = (p < n_points) ? p : (n_points > 0 ? n_points - 1 : 0);

    const float px = pos[pc * 3 + 0];
    const float py = pos[pc * 3 + 1];
    const float pz = pos[pc * 3 + 2];

    const float2* __restrict__ lat = (const float2*)latents;

    /* two-deep software pipeline, halved per-thread state */
    float2 v[2][4];
    float  fr[2][3];

    {
        unsigned idx[4];
        calc_level_half(lp, 0, half, px, py, pz, idx, fr[0][0], fr[0][1], fr[0][2]);
        load_level_half(lat, idx, v[0]);
    }

#pragma unroll
    for (int l = 0; l < NLEVELS; ++l) {
        const int cur = l & 1;
        const int nxt = cur ^ 1;
        if (l + 1 < NLEVELS) {
            unsigned idx[4];
            calc_level_half(lp, l + 1, half, px, py, pz, idx,
                            fr[nxt][0], fr[nxt][1], fr[nxt][2]);
            load_level_half(lat, idx, v[nxt]);
        }

        const float rx = fr[cur][0], ry = fr[cur][1], rz = fr[cur][2];
        const float wy = half ? ry : (1.0f - ry);
        const float wx0 = (1.0f - rx) * wy, wx1 = rx * wy;
        const float wz0 = 1.0f - rz,        wz1 = rz;
        const float w0 = wx0 * wz0, w1 = wx0 * wz1;
        const float w2 = wx1 * wz0, w3 = wx1 * wz1;

        const float2* vv = v[cur];
        float a = w0 * vv[0].x + w1 * vv[1].x + w2 * vv[2].x + w3 * vv[3].x;
        float b = w0 * vv[0].y + w1 * vv[1].y + w2 * vv[2].y + w3 * vv[3].y;

        /* combine the two y-halves within the lane pair */
        a += __shfl_xor_sync(0xffffffffu, a, 1);
        b += __shfl_xor_sync(0xffffffffu, b, 1);

        /* even lane stores feature 2l, odd lane feature 2l+1 */
        const int row = 2 * l + half;
        s_out[row * 129 + pl] = half ? b : a;
    }

    __syncthreads();

    /* coalesced streaming store: 128 pts * 32 floats = 1024 float4 per block */
    const int blockBase = blockIdx.x * (PTS * 32);
#pragma unroll
    for (int i = 0; i < 4; ++i) {
        const int g4 = i * BLOCK + tid;    /* float4 index within block */
        const int g  = g4 * 4;
        const int pp = g >> 5;             /* point-in-block */
        const int c  = g & 31;             /* feature column */
        float4 vs;
        vs.x = s_out[(c + 0) * 129 + pp];
        vs.y = s_out[(c + 1) * 129 + pp];
        vs.z = s_out[(c + 2) * 129 + pp];
        vs.w = s_out[(c + 3) * 129 + pp];
        if (blockBase + g < n_points * 32)
            __stwt(reinterpret_cast<float4*>(out + blockBase + g), vs);
    }
}

static void fill_level_params(LevelParams& lp)
{
    /* mirror reference _level_params() in double precision */
    const double b = exp((log(2048.0) - log(16.0)) / 15.0);
    unsigned off = 0;
    int fhl = 0;
    for (int i = 0; i < NLEVELS; ++i) {
        const double scale = 16.0 * pow(b, (double)i) - 1.0;
        lp.scale[i] = (float)scale;
        const unsigned res = (unsigned)ceil(scale) + 1u;
        lp.res[i] = res;
        unsigned long long n = (unsigned long long)res * res * res;
        lp.off[i] = off;
        if (n <= (unsigned long long)TBL) { fhl += 1; off += (unsigned)n; }
        else                              { off += TBL; }
    }
    lp.fhl = fhl;
}

extern "C" void kernel_launch(void* const* d_in, const int* in_sizes, int n_in,
                              void* d_out, int out_size)
{
    const float* pos     = (const float*)d_in[0];
    const float* latents = (const float*)d_in[1];
    float*       out     = (float*)d_out;

    const int n_points = in_sizes[0] / 3;

    LevelParams lp;
    fill_level_params(lp);

    const int blocks = (n_points + PTS - 1) / PTS;
    hashgrid_enc_kernel<<<blocks, BLOCK>>>(pos, latents, out, n_points, lp);
}